// round 12
// baseline (speedup 1.0000x reference)
#include <cuda_runtime.h>
#include <cuda_bf16.h>
#include <cstdint>

#define NTOK  32768
#define TOKT  2048
#define FD    64
#define AL    48
#define THREADS 448            // 14 warps; cap 144 regs (D1+D2+A fragments ~140)
#define GRID1 148
#define NTILES (NTOK / 16)     // 2048 warp tiles (16 tokens each)

#define TB2    128
#define RSTRIDE 68

typedef unsigned long long ull;

__device__ float g_scores[(size_t)NTOK * AL];

// ---------------- helpers ----------------
__device__ __forceinline__ float sigmoidf_fast(float x) {
    return __fdividef(1.0f, 1.0f + __expf(-x));
}
__device__ __forceinline__ uint32_t pack_bf16x2(float lo, float hi) {
    uint32_t r;
    asm("cvt.rn.bf16x2.f32 %0, %1, %2;" : "=r"(r) : "f"(hi), "f"(lo));
    return r;
}
__device__ __forceinline__ float bf_lo(uint32_t p) { return __uint_as_float(p << 16); }
__device__ __forceinline__ float bf_hi(uint32_t p) { return __uint_as_float(p & 0xFFFF0000u); }

__device__ __forceinline__ void split_pair(float d0, float d1, uint32_t& hi, uint32_t& lo) {
    hi = pack_bf16x2(d0, d1);
    lo = pack_bf16x2(d0 - bf_lo(hi), d1 - bf_hi(hi));
}

__device__ __forceinline__ void mma_acc(float* d, const uint32_t* a, uint32_t b0, uint32_t b1) {
    asm volatile("mma.sync.aligned.m16n8k16.row.col.f32.bf16.bf16.f32 "
        "{%0,%1,%2,%3}, {%4,%5,%6,%7}, {%8,%9}, {%0,%1,%2,%3};"
        : "+f"(d[0]), "+f"(d[1]), "+f"(d[2]), "+f"(d[3])
        : "r"(a[0]), "r"(a[1]), "r"(a[2]), "r"(a[3]), "r"(b0), "r"(b1));
}
__device__ __forceinline__ void mma_zero(float* d, const uint32_t* a, uint32_t b0, uint32_t b1) {
    asm volatile("mma.sync.aligned.m16n8k16.row.col.f32.bf16.bf16.f32 "
        "{%0,%1,%2,%3}, {%4,%5,%6,%7}, {%8,%9}, {%10,%10,%10,%10};"
        : "=f"(d[0]), "=f"(d[1]), "=f"(d[2]), "=f"(d[3])
        : "r"(a[0]), "r"(a[1]), "r"(a[2]), "r"(a[3]), "r"(b0), "r"(b1), "f"(0.0f));
}

__device__ __forceinline__ ull pack2(float x, float y) {
    ull r; asm("mov.b64 %0, {%1, %2};" : "=l"(r) : "f"(x), "f"(y)); return r;
}
__device__ __forceinline__ void unpack2(ull v, float& x, float& y) {
    asm("mov.b64 {%0, %1}, %2;" : "=f"(x), "=f"(y) : "l"(v));
}
__device__ __forceinline__ void ffma2(ull& d, ull a, ull b) {
    asm("fma.rn.f32x2 %0, %1, %2, %0;" : "+l"(d) : "l"(a), "l"(b));
}

// ---------------- Kernel 1: recurrent scan, fused dual-GEMM per iteration ----
// GEMM2(a) [H@W2] and GEMM1(a+1) [H@W1] share A fragments -> one fused
// 192-MMA block per iter, ONE sigmoid/repack phase on the critical path.
__global__ void __launch_bounds__(THREADS, 1)
scan_mma_kernel(const float* __restrict__ he,
                const float* __restrict__ gW1,
                const float* __restrict__ gW2)
{
    __shared__ uint4 sB[2][4][8][32];   // [matrix][kc][ntile][lane] = {bhi0,bhi1,blo0,blo1}

    const int tid = threadIdx.x;
    for (int e = tid; e < 2048; e += THREADS) {
        int m = e >> 10, kc = (e >> 8) & 3, n = (e >> 5) & 7, ln = e & 31;
        int tg = ln & 3, gg = ln >> 2;
        const float* W = m ? gW2 : gW1;
        int k0 = kc * 16 + tg * 2, c = n * 8 + gg;
        uint32_t h0, l0, h1, l1;
        split_pair(W[k0*FD + c],     W[(k0+1)*FD + c], h0, l0);
        split_pair(W[(k0+8)*FD + c], W[(k0+9)*FD + c], h1, l1);
        sB[m][kc][n][ln] = make_uint4(h0, h1, l0, l1);
    }
    __syncthreads();

    const int gw = (tid >> 5) * GRID1 + blockIdx.x;   // transposed tile map
    if (gw >= NTILES) return;
    const int lane = tid & 31, tig = lane & 3, g = lane >> 2;
    const int tok0 = gw * 16;
    const int t0 = tok0 & (TOKT - 1);
    const float* bbase = he + (size_t)(tok0 - t0) * FD;

    // ---- A0 fragments from he rows ----
    uint32_t Ahi[4][4], Alo[4][4];
    #pragma unroll
    for (int kc = 0; kc < 4; ++kc) {
        const float* p0 = he + (size_t)(tok0 + g)     * FD + kc*16 + tig*2;
        const float* p1 = he + (size_t)(tok0 + g + 8) * FD + kc*16 + tig*2;
        float2 v0 = *(const float2*)p0;
        float2 v1 = *(const float2*)p1;
        float2 v2 = *(const float2*)(p0 + 8);
        float2 v3 = *(const float2*)(p1 + 8);
        split_pair(v0.x, v0.y, Ahi[kc][0], Alo[kc][0]);
        split_pair(v1.x, v1.y, Ahi[kc][1], Alo[kc][1]);
        split_pair(v2.x, v2.y, Ahi[kc][2], Alo[kc][2]);
        split_pair(v3.x, v3.y, Ahi[kc][3], Alo[kc][3]);
    }

    float D1[8][4], D2[8][4];

    // ---- prologue: D1 = H0 @ W1 ----
    #pragma unroll
    for (int kc = 0; kc < 4; ++kc)
        #pragma unroll
        for (int n = 0; n < 8; ++n) {
            uint4 b = sB[0][kc][n][lane];
            if (kc == 0) mma_zero(D1[n], Ahi[kc], b.x, b.y);
            else         mma_acc (D1[n], Ahi[kc], b.x, b.y);
            mma_acc(D1[n], Ahi[kc], b.z, b.w);
            mma_acc(D1[n], Alo[kc], b.x, b.y);
        }

    #pragma unroll 1
    for (int a = 0; a < AL; ++a) {
        // ---- A = sigmoid(D1) = H_{a+1}, repacked (only serial phase) ----
        #pragma unroll
        for (int n = 0; n < 8; ++n)
            #pragma unroll
            for (int q = 0; q < 4; ++q)
                D1[n][q] = sigmoidf_fast(D1[n][q]);
        #pragma unroll
        for (int kc = 0; kc < 4; ++kc) {
            split_pair(D1[2*kc  ][0], D1[2*kc  ][1], Ahi[kc][0], Alo[kc][0]);
            split_pair(D1[2*kc  ][2], D1[2*kc  ][3], Ahi[kc][1], Alo[kc][1]);
            split_pair(D1[2*kc+1][0], D1[2*kc+1][1], Ahi[kc][2], Alo[kc][2]);
            split_pair(D1[2*kc+1][2], D1[2*kc+1][3], Ahi[kc][3], Alo[kc][3]);
        }

        // ---- fused block: D2 = A @ W2   and   D1 = A @ W1 (for next iter) ----
        #pragma unroll
        for (int kc = 0; kc < 4; ++kc)
            #pragma unroll
            for (int n = 0; n < 8; ++n) {
                uint4 b2 = sB[1][kc][n][lane];
                uint4 b1 = sB[0][kc][n][lane];
                if (kc == 0) {
                    mma_zero(D2[n], Ahi[kc], b2.x, b2.y);
                    mma_zero(D1[n], Ahi[kc], b1.x, b1.y);
                } else {
                    mma_acc(D2[n], Ahi[kc], b2.x, b2.y);
                    mma_acc(D1[n], Ahi[kc], b1.x, b1.y);
                }
                mma_acc(D2[n], Ahi[kc], b2.z, b2.w);
                mma_acc(D1[n], Ahi[kc], b1.z, b1.w);
                mma_acc(D2[n], Alo[kc], b2.x, b2.y);
                mma_acc(D1[n], Alo[kc], b1.x, b1.y);
            }

        // ---- Y = sigmoid(D2); scores (off the MMA critical path) ----
        #pragma unroll
        for (int n = 0; n < 8; ++n)
            #pragma unroll
            for (int q = 0; q < 4; ++q)
                D2[n][q] = sigmoidf_fast(D2[n][q]);

        #pragma unroll
        for (int hf = 0; hf < 2; ++hf) {
            const int r = hf*8 + g;
            const int t = t0 + r;
            const int L = min(AL, max(t, 1));
            int j = t - L + a;
            if (j < 0) j = 0;
            const float* rp = bbase + (size_t)j * FD + tig * 2;
            float s = 0.f;
            #pragma unroll
            for (int n = 0; n < 8; ++n) {
                float2 v = *(const float2*)(rp + n*8);
                s = fmaf(D2[n][hf*2+0], v.x, s);
                s = fmaf(D2[n][hf*2+1], v.y, s);
            }
            s += __shfl_xor_sync(0xffffffffu, s, 1);
            s += __shfl_xor_sync(0xffffffffu, s, 2);
            if (tig == 0 && a < L)
                g_scores[(size_t)(tok0 + r) * AL + a] = s;
        }
    }
}

// ---------------- Kernel 2: softmax + weighted gather (validated, unchanged) ----
__global__ void __launch_bounds__(TB2, 1)
attn_kernel(const float* __restrict__ he, float* __restrict__ out)
{
    __shared__ float srows[175 * RSTRIDE];

    const int tid   = threadIdx.x;
    const int t0g   = blockIdx.x * TB2;
    const int tseq0 = t0g & (TOKT - 1);
    const float* bbase = he + (size_t)(t0g - tseq0) * FD;

    const int r0    = max(0, tseq0 - AL);
    const int r1    = tseq0 + TB2 - 2;
    const int nrows = r1 - r0 + 1;

    {
        const float4* src = (const float4*)(bbase + (size_t)r0 * FD);
        float4* dst = (float4*)srows;
        for (int i = tid; i < nrows * 16; i += TB2) {
            int r = i >> 4, q = i & 15;
            dst[r * 17 + q] = src[r * 16 + q];
        }
    }
    __syncthreads();

    const int g = t0g + tid;
    const int t = tseq0 + tid;
    const int L = min(AL, max(t, 1));
    const float* scp = g_scores + (size_t)g * AL;

    float s[AL];
    #pragma unroll
    for (int a = 0; a < AL; ++a) {
        float v = scp[a];
        s[a] = (a < L) ? v : -1e30f;
    }
    float m = -1e30f;
    #pragma unroll
    for (int a = 0; a < AL; ++a) m = fmaxf(m, s[a]);

    ull cpair[FD / 2];
    #pragma unroll
    for (int p = 0; p < FD / 2; ++p) cpair[p] = 0ull;
    float ssum = 0.f;

    #pragma unroll 4
    for (int a = 0; a < AL; ++a) {
        float p = __expf(s[a] - m);
        ssum += p;
        int j = t - L + a;
        j = min(max(j, 0), r1);
        const ulonglong2* rp = (const ulonglong2*)(srows + (j - r0) * RSTRIDE);
        ull pp = pack2(p, p);
        #pragma unroll
        for (int q = 0; q < 16; ++q) {
            ulonglong2 v = rp[q];
            ffma2(cpair[2*q],   pp, v.x);
            ffma2(cpair[2*q+1], pp, v.y);
        }
    }

    const float inv = __fdividef(1.0f, ssum);
    float4* o = (float4*)(out + (size_t)g * FD);
    #pragma unroll
    for (int i = 0; i < FD / 4; ++i) {
        float x0, y0, x1, y1;
        unpack2(cpair[2*i],   x0, y0);
        unpack2(cpair[2*i+1], x1, y1);
        float4 v;
        v.x = x0 * inv; v.y = y0 * inv; v.z = x1 * inv; v.w = y1 * inv;
        o[i] = v;
    }
}

extern "C" void kernel_launch(void* const* d_in, const int* in_sizes, int n_in,
                              void* d_out, int out_size)
{
    const float* he = (const float*)d_in[0];   // (16, 2048, 64) f32
    const float* W1 = (const float*)d_in[1];   // (64, 64) f32
    const float* W2 = (const float*)d_in[2];   // (64, 64) f32
    float* out = (float*)d_out;                // (16, 2048, 64) f32

    scan_mma_kernel<<<GRID1, THREADS>>>(he, W1, W2);
    attn_kernel<<<NTOK / TB2, TB2>>>(he, out);
}

// round 13
// speedup vs baseline: 1.2535x; 1.2535x over previous
#include <cuda_runtime.h>
#include <cuda_bf16.h>
#include <cuda_fp16.h>
#include <cstdint>

#define NTOK  32768
#define TOKT  2048
#define FD    64
#define AL    48
#define THREADS 512
#define GRID1 148
#define NTILES (NTOK / 16)     // 2048 warp tiles (16 tokens each)

#define TB2    128
#define RSTRIDE 68

typedef unsigned long long ull;

__device__ float g_scores[(size_t)NTOK * AL];

// ---------------- helpers ----------------
__device__ __forceinline__ float sigmoidf_fast(float x) {
    return __fdividef(1.0f, 1.0f + __expf(-x));
}
__device__ __forceinline__ uint32_t pack_f16x2(float lo_val, float hi_val) {
    // dest low 16 bits <- second src operand (same convention as validated bf16 path)
    uint32_t r;
    asm("cvt.rn.f16x2.f32 %0, %1, %2;" : "=r"(r) : "f"(hi_val), "f"(lo_val));
    return r;
}
// split two f32 into f16x2 hi-pack + f16x2 residual-pack (combined ~2^-22 exact)
__device__ __forceinline__ void split_pair(float d0, float d1, uint32_t& hi, uint32_t& lo) {
    hi = pack_f16x2(d0, d1);
    __half2 h = *reinterpret_cast<__half2*>(&hi);
    lo = pack_f16x2(d0 - __low2float(h), d1 - __high2float(h));
}

__device__ __forceinline__ void mma_acc(float* d, const uint32_t* a, uint32_t b0, uint32_t b1) {
    asm volatile("mma.sync.aligned.m16n8k16.row.col.f32.f16.f16.f32 "
        "{%0,%1,%2,%3}, {%4,%5,%6,%7}, {%8,%9}, {%0,%1,%2,%3};"
        : "+f"(d[0]), "+f"(d[1]), "+f"(d[2]), "+f"(d[3])
        : "r"(a[0]), "r"(a[1]), "r"(a[2]), "r"(a[3]), "r"(b0), "r"(b1));
}
__device__ __forceinline__ void mma_zero(float* d, const uint32_t* a, uint32_t b0, uint32_t b1) {
    asm volatile("mma.sync.aligned.m16n8k16.row.col.f32.f16.f16.f32 "
        "{%0,%1,%2,%3}, {%4,%5,%6,%7}, {%8,%9}, {%10,%10,%10,%10};"
        : "=f"(d[0]), "=f"(d[1]), "=f"(d[2]), "=f"(d[3])
        : "r"(a[0]), "r"(a[1]), "r"(a[2]), "r"(a[3]), "r"(b0), "r"(b1), "f"(0.0f));
}

__device__ __forceinline__ ull pack2(float x, float y) {
    ull r; asm("mov.b64 %0, {%1, %2};" : "=l"(r) : "f"(x), "f"(y)); return r;
}
__device__ __forceinline__ void unpack2(ull v, float& x, float& y) {
    asm("mov.b64 {%0, %1}, %2;" : "=f"(x), "=f"(y) : "l"(v));
}
__device__ __forceinline__ void ffma2(ull& d, ull a, ull b) {
    asm("fma.rn.f32x2 %0, %1, %2, %0;" : "+l"(d) : "l"(a), "l"(b));
}

// ---------------- Kernel 1: recurrent scan via mma.sync fp16 2-term ----------------
// 16 tokens/warp, 16 warps/CTA (R11 structure). A = H split hi+lo fp16 (exact);
// B = fp16(W) single term: computes H @ fp16(W) exactly in fp32 accum.
// 128 HMMA/warp/iter (was 192 with bf16 3-term).
__global__ void __launch_bounds__(THREADS, 1)
scan_mma_kernel(const float* __restrict__ he,
                const float* __restrict__ gW1,
                const float* __restrict__ gW2)
{
    __shared__ uint2 sB[2][4][8][32];   // [matrix][kc][ntile][lane] = {b0, b1} fp16x2

    const int tid = threadIdx.x;
    for (int e = tid; e < 2048; e += THREADS) {
        int m = e >> 10, kc = (e >> 8) & 3, n = (e >> 5) & 7, ln = e & 31;
        int tg = ln & 3, gg = ln >> 2;
        const float* W = m ? gW2 : gW1;
        int k0 = kc * 16 + tg * 2, c = n * 8 + gg;
        uint32_t b0 = pack_f16x2(W[k0*FD + c],     W[(k0+1)*FD + c]);
        uint32_t b1 = pack_f16x2(W[(k0+8)*FD + c], W[(k0+9)*FD + c]);
        sB[m][kc][n][ln] = make_uint2(b0, b1);
    }
    __syncthreads();

    const int gw = (tid >> 5) * GRID1 + blockIdx.x;   // transposed tile map
    if (gw >= NTILES) return;
    const int lane = tid & 31, tig = lane & 3, g = lane >> 2;
    const int tok0 = gw * 16;
    const int t0 = tok0 & (TOKT - 1);
    const float* bbase = he + (size_t)(tok0 - t0) * FD;

    // ---- A0 fragments from he rows (fp16 hi + residual) ----
    uint32_t Ahi[4][4], Alo[4][4];
    #pragma unroll
    for (int kc = 0; kc < 4; ++kc) {
        const float* p0 = he + (size_t)(tok0 + g)     * FD + kc*16 + tig*2;
        const float* p1 = he + (size_t)(tok0 + g + 8) * FD + kc*16 + tig*2;
        float2 v0 = *(const float2*)p0;
        float2 v1 = *(const float2*)p1;
        float2 v2 = *(const float2*)(p0 + 8);
        float2 v3 = *(const float2*)(p1 + 8);
        split_pair(v0.x, v0.y, Ahi[kc][0], Alo[kc][0]);
        split_pair(v1.x, v1.y, Ahi[kc][1], Alo[kc][1]);
        split_pair(v2.x, v2.y, Ahi[kc][2], Alo[kc][2]);
        split_pair(v3.x, v3.y, Ahi[kc][3], Alo[kc][3]);
    }

    float D[8][4];

    #pragma unroll 1
    for (int a = 0; a < AL; ++a) {
        // ---------- GEMM1: D = H @ W1  (2-term: Ahi*B + Alo*B) ----------
        #pragma unroll
        for (int kc = 0; kc < 4; ++kc)
            #pragma unroll
            for (int n = 0; n < 8; ++n) {
                uint2 b = sB[0][kc][n][lane];
                if (kc == 0) mma_zero(D[n], Ahi[kc], b.x, b.y);
                else         mma_acc (D[n], Ahi[kc], b.x, b.y);
                mma_acc(D[n], Alo[kc], b.x, b.y);
            }
        // sigmoid + repack into A fragments (C layout == A half layout)
        #pragma unroll
        for (int n = 0; n < 8; ++n)
            #pragma unroll
            for (int q = 0; q < 4; ++q)
                D[n][q] = sigmoidf_fast(D[n][q]);
        #pragma unroll
        for (int kc = 0; kc < 4; ++kc) {
            split_pair(D[2*kc  ][0], D[2*kc  ][1], Ahi[kc][0], Alo[kc][0]);
            split_pair(D[2*kc  ][2], D[2*kc  ][3], Ahi[kc][1], Alo[kc][1]);
            split_pair(D[2*kc+1][0], D[2*kc+1][1], Ahi[kc][2], Alo[kc][2]);
            split_pair(D[2*kc+1][2], D[2*kc+1][3], Ahi[kc][3], Alo[kc][3]);
        }

        // ---------- GEMM2: D = H_new @ W2 ----------
        #pragma unroll
        for (int kc = 0; kc < 4; ++kc)
            #pragma unroll
            for (int n = 0; n < 8; ++n) {
                uint2 b = sB[1][kc][n][lane];
                if (kc == 0) mma_zero(D[n], Ahi[kc], b.x, b.y);
                else         mma_acc (D[n], Ahi[kc], b.x, b.y);
                mma_acc(D[n], Alo[kc], b.x, b.y);
            }
        // sigmoid -> Y
        #pragma unroll
        for (int n = 0; n < 8; ++n)
            #pragma unroll
            for (int q = 0; q < 4; ++q)
                D[n][q] = sigmoidf_fast(D[n][q]);

        // ---------- scores: sc = <Y_token, he[j]> ----------
        #pragma unroll
        for (int hf = 0; hf < 2; ++hf) {
            const int r = hf*8 + g;
            const int t = t0 + r;
            const int L = min(AL, max(t, 1));
            int j = t - L + a;
            if (j < 0) j = 0;
            const float* rp = bbase + (size_t)j * FD + tig * 2;
            float s = 0.f;
            #pragma unroll
            for (int n = 0; n < 8; ++n) {
                float2 v = *(const float2*)(rp + n*8);
                s = fmaf(D[n][hf*2+0], v.x, s);
                s = fmaf(D[n][hf*2+1], v.y, s);
            }
            s += __shfl_xor_sync(0xffffffffu, s, 1);
            s += __shfl_xor_sync(0xffffffffu, s, 2);
            if (tig == 0 && a < L)
                g_scores[(size_t)(tok0 + r) * AL + a] = s;
        }
    }
}

// ---------------- Kernel 2: softmax + weighted gather (validated, unchanged) ----
__global__ void __launch_bounds__(TB2, 1)
attn_kernel(const float* __restrict__ he, float* __restrict__ out)
{
    __shared__ float srows[175 * RSTRIDE];

    const int tid   = threadIdx.x;
    const int t0g   = blockIdx.x * TB2;
    const int tseq0 = t0g & (TOKT - 1);
    const float* bbase = he + (size_t)(t0g - tseq0) * FD;

    const int r0    = max(0, tseq0 - AL);
    const int r1    = tseq0 + TB2 - 2;
    const int nrows = r1 - r0 + 1;

    {
        const float4* src = (const float4*)(bbase + (size_t)r0 * FD);
        float4* dst = (float4*)srows;
        for (int i = tid; i < nrows * 16; i += TB2) {
            int r = i >> 4, q = i & 15;
            dst[r * 17 + q] = src[r * 16 + q];
        }
    }
    __syncthreads();

    const int g = t0g + tid;
    const int t = tseq0 + tid;
    const int L = min(AL, max(t, 1));
    const float* scp = g_scores + (size_t)g * AL;

    float s[AL];
    #pragma unroll
    for (int a = 0; a < AL; ++a) {
        float v = scp[a];
        s[a] = (a < L) ? v : -1e30f;
    }
    float m = -1e30f;
    #pragma unroll
    for (int a = 0; a < AL; ++a) m = fmaxf(m, s[a]);

    ull cpair[FD / 2];
    #pragma unroll
    for (int p = 0; p < FD / 2; ++p) cpair[p] = 0ull;
    float ssum = 0.f;

    #pragma unroll 4
    for (int a = 0; a < AL; ++a) {
        float p = __expf(s[a] - m);
        ssum += p;
        int j = t - L + a;
        j = min(max(j, 0), r1);
        const ulonglong2* rp = (const ulonglong2*)(srows + (j - r0) * RSTRIDE);
        ull pp = pack2(p, p);
        #pragma unroll
        for (int q = 0; q < 16; ++q) {
            ulonglong2 v = rp[q];
            ffma2(cpair[2*q],   pp, v.x);
            ffma2(cpair[2*q+1], pp, v.y);
        }
    }

    const float inv = __fdividef(1.0f, ssum);
    float4* o = (float4*)(out + (size_t)g * FD);
    #pragma unroll
    for (int i = 0; i < FD / 4; ++i) {
        float x0, y0, x1, y1;
        unpack2(cpair[2*i],   x0, y0);
        unpack2(cpair[2*i+1], x1, y1);
        float4 v;
        v.x = x0 * inv; v.y = y0 * inv; v.z = x1 * inv; v.w = y1 * inv;
        o[i] = v;
    }
}

extern "C" void kernel_launch(void* const* d_in, const int* in_sizes, int n_in,
                              void* d_out, int out_size)
{
    const float* he = (const float*)d_in[0];   // (16, 2048, 64) f32
    const float* W1 = (const float*)d_in[1];   // (64, 64) f32
    const float* W2 = (const float*)d_in[2];   // (64, 64) f32
    float* out = (float*)d_out;                // (16, 2048, 64) f32

    scan_mma_kernel<<<GRID1, THREADS>>>(he, W1, W2);
    attn_kernel<<<NTOK / TB2, TB2>>>(he, out);
}